// round 1
// baseline (speedup 1.0000x reference)
#include <cuda_runtime.h>
#include <cuda_bf16.h>
#include <cstdint>

// Problem constants: B=2, S=2048, D=1024, H=16, HD=64
#define BB   2
#define SS   2048
#define DD   1024
#define HH   16
#define HD   64
#define MDIM (BB*SS)     // 4096
#define NDIM DD          // 1024
#define KDIM DD          // 1024

// Scratch (allocation-free rule: __device__ globals)
__device__ float g_q[BB*HH*SS*HD];     // [B,H,S,HD]
__device__ float g_k[BB*HH*SS*HD];
__device__ float g_v[BB*HH*SS*HD];
__device__ float g_attn[BB*SS*DD];     // [B,S,D]

// ---------------------------------------------------------------------------
// GEMM: C[m,n] = sum_k A[m,k] * W[n,k] + bias[n]
// outmode 0/1/2 -> write q/k/v in [B,H,S,HD] layout; outmode 3 -> row-major Cext,
// reading A from g_attn.
// Tiles: BM=BN=64, BK=16, 256 threads, 4x4 per-thread register tile.
// ---------------------------------------------------------------------------
__global__ void __launch_bounds__(256) gemm_kernel(const float* __restrict__ A,
                                                   const float* __restrict__ W,
                                                   const float* __restrict__ bias,
                                                   float* __restrict__ Cext,
                                                   int outmode)
{
    __shared__ float As[16][68];
    __shared__ float Bs[16][68];

    const int t  = threadIdx.x;
    const int tx = t & 15;
    const int ty = t >> 4;
    const int m0 = blockIdx.y * 64;
    const int n0 = blockIdx.x * 64;

    const int lr = t >> 2;         // 0..63 : row within tile being loaded
    const int lk = (t & 3) << 2;   // 0,4,8,12 : k offset

    const float* Abase = (outmode == 3) ? (const float*)g_attn : A;
    const float* Ap = Abase + (size_t)(m0 + lr) * KDIM + lk;
    const float* Wp = W     + (size_t)(n0 + lr) * KDIM + lk;

    float c[4][4];
#pragma unroll
    for (int i = 0; i < 4; i++)
#pragma unroll
        for (int j = 0; j < 4; j++) c[i][j] = 0.f;

    for (int k0 = 0; k0 < KDIM; k0 += 16) {
        float4 a4 = *(const float4*)(Ap + k0);
        float4 b4 = *(const float4*)(Wp + k0);
        As[lk+0][lr] = a4.x; As[lk+1][lr] = a4.y; As[lk+2][lr] = a4.z; As[lk+3][lr] = a4.w;
        Bs[lk+0][lr] = b4.x; Bs[lk+1][lr] = b4.y; Bs[lk+2][lr] = b4.z; Bs[lk+3][lr] = b4.w;
        __syncthreads();
#pragma unroll
        for (int kk = 0; kk < 16; kk++) {
            float a[4], b[4];
            *(float4*)a = *(const float4*)&As[kk][ty << 2];
            *(float4*)b = *(const float4*)&Bs[kk][tx << 2];
#pragma unroll
            for (int i = 0; i < 4; i++)
#pragma unroll
                for (int j = 0; j < 4; j++)
                    c[i][j] += a[i] * b[j];
        }
        __syncthreads();
    }

    float* dst;
    if      (outmode == 0) dst = g_q;
    else if (outmode == 1) dst = g_k;
    else if (outmode == 2) dst = g_v;
    else                   dst = Cext;

#pragma unroll
    for (int i = 0; i < 4; i++) {
        const int m = m0 + (ty << 2) + i;
        const int b = m >> 11;        // m / S
        const int s = m & (SS - 1);
#pragma unroll
        for (int j = 0; j < 4; j++) {
            const int n = n0 + (tx << 2) + j;
            const float val = c[i][j] + bias[n];
            if (outmode < 3) {
                const int h  = n >> 6;        // n / HD
                const int hd = n & (HD - 1);
                dst[(((size_t)(b * HH + h)) * SS + s) * HD + hd] = val;
            } else {
                dst[(size_t)m * NDIM + n] = val;
            }
        }
    }
}

// ---------------------------------------------------------------------------
// Causal flash attention.
// Grid: (S/64 q-tiles, B*H). Block: 128 threads = 64 rows x 2 HD-halves.
// Q row held in registers (32 floats/thread). Single shared buffer reused for
// K then V per tile; P (probabilities) in 64x65-padded smem.
// ---------------------------------------------------------------------------
__global__ void __launch_bounds__(128) attn_kernel()
{
    __shared__ float KVs[64][64];   // K tile, then V tile
    __shared__ float Ps [64][65];   // scores -> probs

    const int bh   = blockIdx.y;
    const int qt   = (gridDim.x - 1) - blockIdx.x;  // big tiles first
    const int tid  = threadIdx.x;
    const int r    = tid >> 1;      // 0..63 q-row within tile
    const int half = tid & 1;       // which 32-wide HD half
    const int qrow = qt * 64 + r;

    const float* Qb = g_q + (size_t)bh * SS * HD;
    const float* Kb = g_k + (size_t)bh * SS * HD;
    const float* Vb = g_v + (size_t)bh * SS * HD;

    float qv[32];
    {
        const float* qp = Qb + (size_t)qrow * HD + half * 32;
#pragma unroll
        for (int i = 0; i < 8; i++) {
            float4 f = *(const float4*)(qp + i * 4);
            qv[i*4+0] = f.x; qv[i*4+1] = f.y; qv[i*4+2] = f.z; qv[i*4+3] = f.w;
        }
    }

    float acc[32];
#pragma unroll
    for (int i = 0; i < 32; i++) acc[i] = 0.f;
    float mrow = -1e30f, lrow = 0.f;
    const float scale = 0.125f;   // 1/sqrt(64)

    for (int kt = 0; kt <= qt; kt++) {
        __syncthreads();  // previous iteration's V/P reads complete

        // load K tile (fully coalesced: contiguous 512B per warp per step)
        {
            const float* Kp = Kb + (size_t)kt * 64 * HD;
#pragma unroll
            for (int i = 0; i < 8; i++) {
                const int idx = tid + i * 128;
                const int rr  = idx >> 4;
                const int cc  = (idx & 15) << 2;
                *(float4*)&KVs[rr][cc] = *(const float4*)(Kp + rr * HD + cc);
            }
        }
        __syncthreads();

        float tmax = -1e30f;
        const bool diag = (kt == qt);
#pragma unroll 4
        for (int j = 0; j < 64; j++) {
            float partial = 0.f;
#pragma unroll
            for (int i = 0; i < 8; i++) {
                float4 k4 = *(const float4*)&KVs[j][half * 32 + i * 4];
                partial += qv[i*4+0]*k4.x + qv[i*4+1]*k4.y
                         + qv[i*4+2]*k4.z + qv[i*4+3]*k4.w;
            }
            float s = (partial + __shfl_xor_sync(0xffffffffu, partial, 1)) * scale;
            if (diag && j > r) s = -1e30f;
            tmax = fmaxf(tmax, s);
            if ((j & 1) == half) Ps[r][j] = s;   // pair splits the stores
        }

        const float m_new = fmaxf(mrow, tmax);
        const float alpha = __expf(mrow - m_new);
        __syncthreads();  // Ps scores visible; KVs score-reads done

        // load V tile into same buffer
        {
            const float* Vp = Vb + (size_t)kt * 64 * HD;
#pragma unroll
            for (int i = 0; i < 8; i++) {
                const int idx = tid + i * 128;
                const int rr  = idx >> 4;
                const int cc  = (idx & 15) << 2;
                *(float4*)&KVs[rr][cc] = *(const float4*)(Vp + rr * HD + cc);
            }
        }

        // exponentiate own half of the row's scores
        float lsum = 0.f;
#pragma unroll 8
        for (int jj = 0; jj < 32; jj++) {
            const int j = half * 32 + jj;
            const float p = __expf(Ps[r][j] - m_new);
            lsum += p;
            Ps[r][j] = p;
        }
        lsum += __shfl_xor_sync(0xffffffffu, lsum, 1);
        lrow = lrow * alpha + lsum;
        mrow = m_new;
#pragma unroll
        for (int i = 0; i < 32; i++) acc[i] *= alpha;
        __syncthreads();  // V loaded, probs written

        // acc += P @ V
#pragma unroll 4
        for (int j = 0; j < 64; j++) {
            const float p = Ps[r][j];
#pragma unroll
            for (int i = 0; i < 8; i++) {
                float4 v4 = *(const float4*)&KVs[j][half * 32 + i * 4];
                acc[i*4+0] += p * v4.x;
                acc[i*4+1] += p * v4.y;
                acc[i*4+2] += p * v4.z;
                acc[i*4+3] += p * v4.w;
            }
        }
    }

    // finalize and write [B,S,D]
    const int b = bh >> 4, h = bh & 15;
    const float inv = 1.f / lrow;
    float* op = g_attn + ((size_t)(b * SS + qrow)) * DD + h * HD + half * 32;
#pragma unroll
    for (int i = 0; i < 8; i++) {
        float4 f;
        f.x = acc[i*4+0] * inv; f.y = acc[i*4+1] * inv;
        f.z = acc[i*4+2] * inv; f.w = acc[i*4+3] * inv;
        *(float4*)(op + i * 4) = f;
    }
}

// ---------------------------------------------------------------------------
extern "C" void kernel_launch(void* const* d_in, const int* in_sizes, int n_in,
                              void* d_out, int out_size)
{
    const float* x  = (const float*)d_in[0];
    const float* qw = (const float*)d_in[1];
    const float* qb = (const float*)d_in[2];
    const float* kw = (const float*)d_in[3];
    const float* kb = (const float*)d_in[4];
    const float* vw = (const float*)d_in[5];
    const float* vb = (const float*)d_in[6];
    const float* ow = (const float*)d_in[7];
    const float* ob = (const float*)d_in[8];
    float* out = (float*)d_out;

    dim3 gblk(256);
    dim3 ggrd(NDIM / 64, MDIM / 64);

    gemm_kernel<<<ggrd, gblk>>>(x, qw, qb, nullptr, 0);
    gemm_kernel<<<ggrd, gblk>>>(x, kw, kb, nullptr, 1);
    gemm_kernel<<<ggrd, gblk>>>(x, vw, vb, nullptr, 2);

    attn_kernel<<<dim3(SS / 64, BB * HH), 128>>>();

    gemm_kernel<<<ggrd, gblk>>>(x /*ignored*/, ow, ob, out, 3);
}

// round 2
// speedup vs baseline: 1.3589x; 1.3589x over previous
#include <cuda_runtime.h>
#include <cuda_bf16.h>
#include <cstdint>

// Problem constants: B=2, S=2048, D=1024, H=16, HD=64
#define BB   2
#define SS   2048
#define DD   1024
#define HH   16
#define HD   64
#define MDIM (BB*SS)     // 4096
#define KD   DD          // 1024 (reduction dim of all GEMMs)

// Scratch (allocation-free rule: __device__ globals)
__device__ float g_q[BB*HH*SS*HD];     // [B,H,S,HD]
__device__ float g_k[BB*HH*SS*HD];
__device__ float g_v[BB*HH*SS*HD];
__device__ float g_attn[BB*SS*DD];     // [B,S,D]

// ---------------------------------------------------------------------------
// helpers
// ---------------------------------------------------------------------------
__device__ __forceinline__ uint32_t f2tf(float x) {
    uint32_t r;
    asm("cvt.rna.tf32.f32 %0, %1;" : "=r"(r) : "f"(x));
    return r;
}

__device__ __forceinline__ void mma_tf32(float* c, const uint32_t* a, const uint32_t* b) {
    asm volatile(
        "mma.sync.aligned.m16n8k8.row.col.f32.tf32.tf32.f32 "
        "{%0,%1,%2,%3}, {%4,%5,%6,%7}, {%8,%9}, {%0,%1,%2,%3};"
        : "+f"(c[0]), "+f"(c[1]), "+f"(c[2]), "+f"(c[3])
        : "r"(a[0]), "r"(a[1]), "r"(a[2]), "r"(a[3]),
          "r"(b[0]), "r"(b[1]));
}

__device__ __forceinline__ void cpa16(void* smem, const void* g) {
    uint32_t s = (uint32_t)__cvta_generic_to_shared(smem);
    asm volatile("cp.async.cg.shared.global [%0], [%1], 16;" :: "r"(s), "l"(g) : "memory");
}

// ---------------------------------------------------------------------------
// TF32 tensor-core GEMM: C[m,n] = sum_k A[m,k] * W[n,k] + bias[n]
// BM=128, BN=128, BK=16, 256 threads, double-buffered cp.async.
// Warp grid 4(m) x 2(n); warp tile 32x64 = 2x8 m16n8k8 MMA tiles.
// outmode 0/1/2 -> scatter into g_q/g_k/g_v [B,H,S,HD]; 3 -> row-major Cext
// (reading A from g_attn).
// ---------------------------------------------------------------------------
#define PADK 20   // 16 + 4 pad: conflict-free frag LDS, rows stay 16B aligned

__global__ void __launch_bounds__(256) gemm_tc(const float* __restrict__ A,
                                               const float* __restrict__ W,
                                               const float* __restrict__ bias,
                                               float* __restrict__ Cext,
                                               int outmode)
{
    __shared__ float sA[2][128 * PADK];
    __shared__ float sW[2][128 * PADK];

    const int t    = threadIdx.x;
    const int lane = t & 31;
    const int warp = t >> 5;
    const int wm   = warp & 3;            // 4 warps along M
    const int wn   = warp >> 2;           // 2 warps along N
    const int m0   = blockIdx.y * 128;
    const int n0   = blockIdx.x * 128;

    const float* Abase = (outmode == 3) ? (const float*)g_attn : A;

    float c[2][8][4];
#pragma unroll
    for (int mt = 0; mt < 2; mt++)
#pragma unroll
        for (int nt = 0; nt < 8; nt++)
#pragma unroll
            for (int i = 0; i < 4; i++) c[mt][nt][i] = 0.f;

    // stage loader: 512 float4 per operand tile, 2 per thread per operand
    auto issue = [&](int kt, int buf) {
        const int k0 = kt * 16;
#pragma unroll
        for (int i = 0; i < 2; i++) {
            const int idx = t + i * 256;      // 0..511
            const int row = idx >> 2;         // 0..127
            const int c4  = (idx & 3) << 2;   // 0,4,8,12
            cpa16(&sA[buf][row * PADK + c4], Abase + (size_t)(m0 + row) * KD + k0 + c4);
            cpa16(&sW[buf][row * PADK + c4], W     + (size_t)(n0 + row) * KD + k0 + c4);
        }
        asm volatile("cp.async.commit_group;" ::: "memory");
    };

    issue(0, 0);
    const int NK = KD / 16;   // 64 stages

    const int g    = lane >> 2;   // 0..7
    const int kq   = lane & 3;    // 0..3

    for (int kt = 0; kt < NK; kt++) {
        asm volatile("cp.async.wait_group 0;" ::: "memory");
        __syncthreads();
        if (kt + 1 < NK) issue(kt + 1, (kt + 1) & 1);

        const float* a = &sA[kt & 1][0];
        const float* w = &sW[kt & 1][0];

#pragma unroll
        for (int ks = 0; ks < 2; ks++) {
            const int krow = ks * 8 + kq;
            uint32_t af[2][4], bf[8][2];
#pragma unroll
            for (int mt = 0; mt < 2; mt++) {
                const int rb = wm * 32 + mt * 16 + g;
                af[mt][0] = f2tf(a[rb * PADK + krow]);
                af[mt][1] = f2tf(a[(rb + 8) * PADK + krow]);
                af[mt][2] = f2tf(a[rb * PADK + krow + 4]);
                af[mt][3] = f2tf(a[(rb + 8) * PADK + krow + 4]);
            }
#pragma unroll
            for (int nt = 0; nt < 8; nt++) {
                const int nb = wn * 64 + nt * 8 + g;
                bf[nt][0] = f2tf(w[nb * PADK + krow]);
                bf[nt][1] = f2tf(w[nb * PADK + krow + 4]);
            }
#pragma unroll
            for (int mt = 0; mt < 2; mt++)
#pragma unroll
                for (int nt = 0; nt < 8; nt++)
                    mma_tf32(c[mt][nt], af[mt], bf[nt]);
        }
        __syncthreads();
    }

    // epilogue: bias + scatter
    float* dst;
    if      (outmode == 0) dst = g_q;
    else if (outmode == 1) dst = g_k;
    else if (outmode == 2) dst = g_v;
    else                   dst = Cext;

#pragma unroll
    for (int mt = 0; mt < 2; mt++) {
        const int r0 = m0 + wm * 32 + mt * 16 + g;   // and r0+8
#pragma unroll
        for (int nt = 0; nt < 8; nt++) {
            const int n  = n0 + wn * 64 + nt * 8 + (kq << 1);
            const float b0 = bias[n], b1 = bias[n + 1];
#pragma unroll
            for (int half = 0; half < 2; half++) {
                const int r = r0 + half * 8;
                const float v0 = c[mt][nt][half * 2 + 0] + b0;
                const float v1 = c[mt][nt][half * 2 + 1] + b1;
                if (outmode < 3) {
                    const int b  = r >> 11;          // r / S
                    const int s  = r & (SS - 1);
                    const int h  = n >> 6;           // n / HD
                    const int hd = n & (HD - 1);
                    float2* p = (float2*)&dst[(((size_t)(b * HH + h)) * SS + s) * HD + hd];
                    *p = make_float2(v0, v1);
                } else {
                    float2* p = (float2*)&dst[(size_t)r * DD + n];
                    *p = make_float2(v0, v1);
                }
            }
        }
    }
}

// ---------------------------------------------------------------------------
// Causal flash attention (unchanged from round 1).
// Grid: (S/64 q-tiles, B*H). Block: 128 threads = 64 rows x 2 HD-halves.
// ---------------------------------------------------------------------------
__global__ void __launch_bounds__(128) attn_kernel()
{
    __shared__ float KVs[64][64];   // K tile, then V tile
    __shared__ float Ps [64][65];   // scores -> probs

    const int bh   = blockIdx.y;
    const int qt   = (gridDim.x - 1) - blockIdx.x;  // big tiles first
    const int tid  = threadIdx.x;
    const int r    = tid >> 1;      // 0..63 q-row within tile
    const int half = tid & 1;       // which 32-wide HD half
    const int qrow = qt * 64 + r;

    const float* Qb = g_q + (size_t)bh * SS * HD;
    const float* Kb = g_k + (size_t)bh * SS * HD;
    const float* Vb = g_v + (size_t)bh * SS * HD;

    float qv[32];
    {
        const float* qp = Qb + (size_t)qrow * HD + half * 32;
#pragma unroll
        for (int i = 0; i < 8; i++) {
            float4 f = *(const float4*)(qp + i * 4);
            qv[i*4+0] = f.x; qv[i*4+1] = f.y; qv[i*4+2] = f.z; qv[i*4+3] = f.w;
        }
    }

    float acc[32];
#pragma unroll
    for (int i = 0; i < 32; i++) acc[i] = 0.f;
    float mrow = -1e30f, lrow = 0.f;
    const float scale = 0.125f;   // 1/sqrt(64)

    for (int kt = 0; kt <= qt; kt++) {
        __syncthreads();

        {
            const float* Kp = Kb + (size_t)kt * 64 * HD;
#pragma unroll
            for (int i = 0; i < 8; i++) {
                const int idx = tid + i * 128;
                const int rr  = idx >> 4;
                const int cc  = (idx & 15) << 2;
                *(float4*)&KVs[rr][cc] = *(const float4*)(Kp + rr * HD + cc);
            }
        }
        __syncthreads();

        float tmax = -1e30f;
        const bool diag = (kt == qt);
#pragma unroll 4
        for (int j = 0; j < 64; j++) {
            float partial = 0.f;
#pragma unroll
            for (int i = 0; i < 8; i++) {
                float4 k4 = *(const float4*)&KVs[j][half * 32 + i * 4];
                partial += qv[i*4+0]*k4.x + qv[i*4+1]*k4.y
                         + qv[i*4+2]*k4.z + qv[i*4+3]*k4.w;
            }
            float s = (partial + __shfl_xor_sync(0xffffffffu, partial, 1)) * scale;
            if (diag && j > r) s = -1e30f;
            tmax = fmaxf(tmax, s);
            if ((j & 1) == half) Ps[r][j] = s;
        }

        const float m_new = fmaxf(mrow, tmax);
        const float alpha = __expf(mrow - m_new);
        __syncthreads();

        {
            const float* Vp = Vb + (size_t)kt * 64 * HD;
#pragma unroll
            for (int i = 0; i < 8; i++) {
                const int idx = tid + i * 128;
                const int rr  = idx >> 4;
                const int cc  = (idx & 15) << 2;
                *(float4*)&KVs[rr][cc] = *(const float4*)(Vp + rr * HD + cc);
            }
        }

        float lsum = 0.f;
#pragma unroll 8
        for (int jj = 0; jj < 32; jj++) {
            const int j = half * 32 + jj;
            const float p = __expf(Ps[r][j] - m_new);
            lsum += p;
            Ps[r][j] = p;
        }
        lsum += __shfl_xor_sync(0xffffffffu, lsum, 1);
        lrow = lrow * alpha + lsum;
        mrow = m_new;
#pragma unroll
        for (int i = 0; i < 32; i++) acc[i] *= alpha;
        __syncthreads();

#pragma unroll 4
        for (int j = 0; j < 64; j++) {
            const float p = Ps[r][j];
#pragma unroll
            for (int i = 0; i < 8; i++) {
                float4 v4 = *(const float4*)&KVs[j][half * 32 + i * 4];
                acc[i*4+0] += p * v4.x;
                acc[i*4+1] += p * v4.y;
                acc[i*4+2] += p * v4.z;
                acc[i*4+3] += p * v4.w;
            }
        }
    }

    const int b = bh >> 4, h = bh & 15;
    const float inv = 1.f / lrow;
    float* op = g_attn + ((size_t)(b * SS + qrow)) * DD + h * HD + half * 32;
#pragma unroll
    for (int i = 0; i < 8; i++) {
        float4 f;
        f.x = acc[i*4+0] * inv; f.y = acc[i*4+1] * inv;
        f.z = acc[i*4+2] * inv; f.w = acc[i*4+3] * inv;
        *(float4*)(op + i * 4) = f;
    }
}

// ---------------------------------------------------------------------------
extern "C" void kernel_launch(void* const* d_in, const int* in_sizes, int n_in,
                              void* d_out, int out_size)
{
    const float* x  = (const float*)d_in[0];
    const float* qw = (const float*)d_in[1];
    const float* qb = (const float*)d_in[2];
    const float* kw = (const float*)d_in[3];
    const float* kb = (const float*)d_in[4];
    const float* vw = (const float*)d_in[5];
    const float* vb = (const float*)d_in[6];
    const float* ow = (const float*)d_in[7];
    const float* ob = (const float*)d_in[8];
    float* out = (float*)d_out;

    dim3 gblk(256);
    dim3 ggrd(DD / 128, MDIM / 128);   // (8, 32)

    gemm_tc<<<ggrd, gblk>>>(x, qw, qb, nullptr, 0);
    gemm_tc<<<ggrd, gblk>>>(x, kw, kb, nullptr, 1);
    gemm_tc<<<ggrd, gblk>>>(x, vw, vb, nullptr, 2);

    attn_kernel<<<dim3(SS / 64, BB * HH), 128>>>();

    gemm_tc<<<ggrd, gblk>>>(x /*ignored*/, ow, ob, out, 3);
}

// round 3
// speedup vs baseline: 3.9297x; 2.8919x over previous
#include <cuda_runtime.h>
#include <cuda_bf16.h>
#include <cstdint>

// Problem constants: B=2, S=2048, D=1024, H=16, HD=64
#define BB   2
#define SS   2048
#define DD   1024
#define HH   16
#define HD   64
#define MDIM (BB*SS)     // 4096
#define KD   DD          // 1024 (reduction dim of all GEMMs)

// Scratch (allocation-free rule: __device__ globals)
__device__ float g_q[BB*HH*SS*HD];     // [B,H,S,HD]
__device__ float g_k[BB*HH*SS*HD];
__device__ float g_v[BB*HH*SS*HD];
__device__ float g_attn[BB*SS*DD];     // [B,S,D]

// ---------------------------------------------------------------------------
// helpers
// ---------------------------------------------------------------------------
__device__ __forceinline__ uint32_t f2tf(float x) {
    uint32_t r;
    asm("cvt.rna.tf32.f32 %0, %1;" : "=r"(r) : "f"(x));
    return r;
}

__device__ __forceinline__ void mma_tf32(float* c, const uint32_t* a, const uint32_t* b) {
    asm volatile(
        "mma.sync.aligned.m16n8k8.row.col.f32.tf32.tf32.f32 "
        "{%0,%1,%2,%3}, {%4,%5,%6,%7}, {%8,%9}, {%0,%1,%2,%3};"
        : "+f"(c[0]), "+f"(c[1]), "+f"(c[2]), "+f"(c[3])
        : "r"(a[0]), "r"(a[1]), "r"(a[2]), "r"(a[3]),
          "r"(b[0]), "r"(b[1]));
}

__device__ __forceinline__ void cpa16(void* smem, const void* g) {
    uint32_t s = (uint32_t)__cvta_generic_to_shared(smem);
    asm volatile("cp.async.cg.shared.global [%0], [%1], 16;" :: "r"(s), "l"(g) : "memory");
}

// ---------------------------------------------------------------------------
// TF32 tensor-core GEMM (unchanged from round 2).
// C[m,n] = sum_k A[m,k] * W[n,k] + bias[n]
// ---------------------------------------------------------------------------
#define PADK 20

__global__ void __launch_bounds__(256) gemm_tc(const float* __restrict__ A,
                                               const float* __restrict__ W,
                                               const float* __restrict__ bias,
                                               float* __restrict__ Cext,
                                               int outmode)
{
    __shared__ float sA[2][128 * PADK];
    __shared__ float sW[2][128 * PADK];

    const int t    = threadIdx.x;
    const int lane = t & 31;
    const int warp = t >> 5;
    const int wm   = warp & 3;
    const int wn   = warp >> 2;
    const int m0   = blockIdx.y * 128;
    const int n0   = blockIdx.x * 128;

    const float* Abase = (outmode == 3) ? (const float*)g_attn : A;

    float c[2][8][4];
#pragma unroll
    for (int mt = 0; mt < 2; mt++)
#pragma unroll
        for (int nt = 0; nt < 8; nt++)
#pragma unroll
            for (int i = 0; i < 4; i++) c[mt][nt][i] = 0.f;

    auto issue = [&](int kt, int buf) {
        const int k0 = kt * 16;
#pragma unroll
        for (int i = 0; i < 2; i++) {
            const int idx = t + i * 256;
            const int row = idx >> 2;
            const int c4  = (idx & 3) << 2;
            cpa16(&sA[buf][row * PADK + c4], Abase + (size_t)(m0 + row) * KD + k0 + c4);
            cpa16(&sW[buf][row * PADK + c4], W     + (size_t)(n0 + row) * KD + k0 + c4);
        }
        asm volatile("cp.async.commit_group;" ::: "memory");
    };

    issue(0, 0);
    const int NK = KD / 16;

    const int g  = lane >> 2;
    const int kq = lane & 3;

    for (int kt = 0; kt < NK; kt++) {
        asm volatile("cp.async.wait_group 0;" ::: "memory");
        __syncthreads();
        if (kt + 1 < NK) issue(kt + 1, (kt + 1) & 1);

        const float* a = &sA[kt & 1][0];
        const float* w = &sW[kt & 1][0];

#pragma unroll
        for (int ks = 0; ks < 2; ks++) {
            const int krow = ks * 8 + kq;
            uint32_t af[2][4], bf[8][2];
#pragma unroll
            for (int mt = 0; mt < 2; mt++) {
                const int rb = wm * 32 + mt * 16 + g;
                af[mt][0] = f2tf(a[rb * PADK + krow]);
                af[mt][1] = f2tf(a[(rb + 8) * PADK + krow]);
                af[mt][2] = f2tf(a[rb * PADK + krow + 4]);
                af[mt][3] = f2tf(a[(rb + 8) * PADK + krow + 4]);
            }
#pragma unroll
            for (int nt = 0; nt < 8; nt++) {
                const int nb = wn * 64 + nt * 8 + g;
                bf[nt][0] = f2tf(w[nb * PADK + krow]);
                bf[nt][1] = f2tf(w[nb * PADK + krow + 4]);
            }
#pragma unroll
            for (int mt = 0; mt < 2; mt++)
#pragma unroll
                for (int nt = 0; nt < 8; nt++)
                    mma_tf32(c[mt][nt], af[mt], bf[nt]);
        }
        __syncthreads();
    }

    float* dst;
    if      (outmode == 0) dst = g_q;
    else if (outmode == 1) dst = g_k;
    else if (outmode == 2) dst = g_v;
    else                   dst = Cext;

#pragma unroll
    for (int mt = 0; mt < 2; mt++) {
        const int r0 = m0 + wm * 32 + mt * 16 + g;
#pragma unroll
        for (int nt = 0; nt < 8; nt++) {
            const int n  = n0 + wn * 64 + nt * 8 + (kq << 1);
            const float b0 = bias[n], b1 = bias[n + 1];
#pragma unroll
            for (int half = 0; half < 2; half++) {
                const int r = r0 + half * 8;
                const float v0 = c[mt][nt][half * 2 + 0] + b0;
                const float v1 = c[mt][nt][half * 2 + 1] + b1;
                if (outmode < 3) {
                    const int b  = r >> 11;
                    const int s  = r & (SS - 1);
                    const int h  = n >> 6;
                    const int hd = n & (HD - 1);
                    float2* p = (float2*)&dst[(((size_t)(b * HH + h)) * SS + s) * HD + hd];
                    *p = make_float2(v0, v1);
                } else {
                    float2* p = (float2*)&dst[(size_t)r * DD + n];
                    *p = make_float2(v0, v1);
                }
            }
        }
    }
}

// ---------------------------------------------------------------------------
// Tensor-core causal flash attention (TF32 mma.sync).
// Grid: (S/64 q-tiles, B*H). Block: 128 threads = 4 warps x 16 q-rows.
// K/V tiles in XOR-swizzled smem; Q as register A-fragments; scores kept in
// MMA C-layout for online softmax; P converted C->A layout via shuffles.
// ---------------------------------------------------------------------------
// Swizzled tile copy: 64x64 floats, source is contiguous (4096 floats).
__device__ __forceinline__ void load_tile_sw(float* dst, const float* src, int tid) {
#pragma unroll
    for (int i = 0; i < 8; i++) {
        const int idx = tid + i * 128;     // 0..1023 float4s
        const int rr  = idx >> 4;
        const int cc  = (idx & 15) << 2;
        float4 f = *(const float4*)(src + idx * 4);
        *(float4*)(dst + rr * 64 + (cc ^ ((rr & 7) << 2))) = f;
    }
}

__global__ void __launch_bounds__(128) attn_tc()
{
    __shared__ float Ks[64 * 64];
    __shared__ float Vs[64 * 64];

    const int bh   = blockIdx.y;
    const int qt   = (gridDim.x - 1) - blockIdx.x;  // big tiles first
    const int tid  = threadIdx.x;
    const int lane = tid & 31;
    const int warp = tid >> 5;
    const int g    = lane >> 2;   // 0..7
    const int kq   = lane & 3;    // 0..3

    const float* Qb = g_q + (size_t)bh * SS * HD;
    const float* Kb = g_k + (size_t)bh * SS * HD;
    const float* Vb = g_v + (size_t)bh * SS * HD;

    // ---- load Q tile into Ks (swizzled), extract A-fragments ----
    load_tile_sw(Ks, Qb + (size_t)qt * 64 * HD, tid);
    __syncthreads();

    uint32_t qf[8][4];
    {
        const int r0 = warp * 16 + g;
        const int r1 = r0 + 8;
        const int s0 = (r0 & 7) << 2;
        const int s1 = (r1 & 7) << 2;
#pragma unroll
        for (int ks = 0; ks < 8; ks++) {
            const int c0 = ks * 8 + kq;
            qf[ks][0] = f2tf(Ks[r0 * 64 + (c0 ^ s0)]);
            qf[ks][1] = f2tf(Ks[r1 * 64 + (c0 ^ s1)]);
            qf[ks][2] = f2tf(Ks[r0 * 64 + ((c0 + 4) ^ s0)]);
            qf[ks][3] = f2tf(Ks[r1 * 64 + ((c0 + 4) ^ s1)]);
        }
    }

    float acc[8][4];
#pragma unroll
    for (int nt = 0; nt < 8; nt++)
#pragma unroll
        for (int i = 0; i < 4; i++) acc[nt][i] = 0.f;
    float m0 = -1e30f, m1 = -1e30f, l0 = 0.f, l1 = 0.f;
    const float scale = 0.125f;   // 1/sqrt(64)

    const int row0 = warp * 16 + g;   // q-row within tile (and row0+8)

    for (int kt = 0; kt <= qt; kt++) {
        __syncthreads();   // previous iteration's smem reads complete
        load_tile_sw(Ks, Kb + (size_t)kt * 64 * HD, tid);
        load_tile_sw(Vs, Vb + (size_t)kt * 64 * HD, tid);
        __syncthreads();

        // ---- S = Q @ K^T ----
        float c[8][4];
#pragma unroll
        for (int nt = 0; nt < 8; nt++)
#pragma unroll
            for (int i = 0; i < 4; i++) c[nt][i] = 0.f;

#pragma unroll
        for (int ks = 0; ks < 8; ks++) {
            const int kcol = ks * 8 + kq;
#pragma unroll
            for (int nt = 0; nt < 8; nt++) {
                const int krow = nt * 8 + g;
                const int sw   = g << 2;
                uint32_t b[2];
                b[0] = f2tf(Ks[krow * 64 + (kcol ^ sw)]);
                b[1] = f2tf(Ks[krow * 64 + ((kcol + 4) ^ sw)]);
                mma_tf32(c[nt], qf[ks], b);
            }
        }

        // ---- scale + causal mask ----
        const bool diag = (kt == qt);
#pragma unroll
        for (int nt = 0; nt < 8; nt++) {
            const int colb = nt * 8 + (kq << 1);
#pragma unroll
            for (int i = 0; i < 4; i++) {
                float v = c[nt][i] * scale;
                if (diag) {
                    const int col = colb + (i & 1);
                    const int row = row0 + ((i & 2) << 2);  // +8 for i>=2
                    if (col > row) v = -1e30f;
                }
                c[nt][i] = v;
            }
        }

        // ---- online softmax (rows row0 and row0+8) ----
        float t0 = -1e30f, t1 = -1e30f;
#pragma unroll
        for (int nt = 0; nt < 8; nt++) {
            t0 = fmaxf(t0, fmaxf(c[nt][0], c[nt][1]));
            t1 = fmaxf(t1, fmaxf(c[nt][2], c[nt][3]));
        }
        t0 = fmaxf(t0, __shfl_xor_sync(0xffffffffu, t0, 1));
        t0 = fmaxf(t0, __shfl_xor_sync(0xffffffffu, t0, 2));
        t1 = fmaxf(t1, __shfl_xor_sync(0xffffffffu, t1, 1));
        t1 = fmaxf(t1, __shfl_xor_sync(0xffffffffu, t1, 2));

        const float mn0 = fmaxf(m0, t0);
        const float mn1 = fmaxf(m1, t1);
        const float a0  = __expf(m0 - mn0);
        const float a1  = __expf(m1 - mn1);

        float s0 = 0.f, s1 = 0.f;
#pragma unroll
        for (int nt = 0; nt < 8; nt++) {
            c[nt][0] = __expf(c[nt][0] - mn0);
            c[nt][1] = __expf(c[nt][1] - mn0);
            c[nt][2] = __expf(c[nt][2] - mn1);
            c[nt][3] = __expf(c[nt][3] - mn1);
            s0 += c[nt][0] + c[nt][1];
            s1 += c[nt][2] + c[nt][3];
        }
        s0 += __shfl_xor_sync(0xffffffffu, s0, 1);
        s0 += __shfl_xor_sync(0xffffffffu, s0, 2);
        s1 += __shfl_xor_sync(0xffffffffu, s1, 1);
        s1 += __shfl_xor_sync(0xffffffffu, s1, 2);

        l0 = l0 * a0 + s0;  m0 = mn0;
        l1 = l1 * a1 + s1;  m1 = mn1;

#pragma unroll
        for (int nt = 0; nt < 8; nt++) {
            acc[nt][0] *= a0; acc[nt][1] *= a0;
            acc[nt][2] *= a1; acc[nt][3] *= a1;
        }

        // ---- O += P @ V : convert P C-layout -> A-layout via shuffles ----
        const int src1 = (lane & ~3) | (kq >> 1);
        const int src2 = src1 + 2;
#pragma unroll
        for (int ks = 0; ks < 8; ks++) {
            const float x0 = __shfl_sync(0xffffffffu, c[ks][0], src1);
            const float x1 = __shfl_sync(0xffffffffu, c[ks][1], src1);
            const float y0 = __shfl_sync(0xffffffffu, c[ks][0], src2);
            const float y1 = __shfl_sync(0xffffffffu, c[ks][1], src2);
            const float z0 = __shfl_sync(0xffffffffu, c[ks][2], src1);
            const float z1 = __shfl_sync(0xffffffffu, c[ks][3], src1);
            const float w0 = __shfl_sync(0xffffffffu, c[ks][2], src2);
            const float w1 = __shfl_sync(0xffffffffu, c[ks][3], src2);
            uint32_t pa[4];
            pa[0] = f2tf((kq & 1) ? x1 : x0);
            pa[1] = f2tf((kq & 1) ? z1 : z0);
            pa[2] = f2tf((kq & 1) ? y1 : y0);
            pa[3] = f2tf((kq & 1) ? w1 : w0);

            const int vr0 = ks * 8 + kq;       // V row for b[0]
            const int vr1 = vr0 + 4;           // V row for b[1]
            const int sw0 = (vr0 & 7) << 2;
            const int sw1 = (vr1 & 7) << 2;
#pragma unroll
            for (int nt = 0; nt < 8; nt++) {
                const int vc = nt * 8 + g;
                uint32_t b[2];
                b[0] = f2tf(Vs[vr0 * 64 + (vc ^ sw0)]);
                b[1] = f2tf(Vs[vr1 * 64 + (vc ^ sw1)]);
                mma_tf32(acc[nt], pa, b);
            }
        }
    }

    // ---- finalize: normalize and write [B,S,D] ----
    const int b = bh >> 4, h = bh & 15;
    const float inv0 = 1.f / l0;
    const float inv1 = 1.f / l1;
    const int qr0 = qt * 64 + row0;
    const int qr1 = qr0 + 8;
#pragma unroll
    for (int nt = 0; nt < 8; nt++) {
        const int col = h * HD + nt * 8 + (kq << 1);
        float2* p0 = (float2*)&g_attn[((size_t)(b * SS + qr0)) * DD + col];
        float2* p1 = (float2*)&g_attn[((size_t)(b * SS + qr1)) * DD + col];
        *p0 = make_float2(acc[nt][0] * inv0, acc[nt][1] * inv0);
        *p1 = make_float2(acc[nt][2] * inv1, acc[nt][3] * inv1);
    }
}

// ---------------------------------------------------------------------------
extern "C" void kernel_launch(void* const* d_in, const int* in_sizes, int n_in,
                              void* d_out, int out_size)
{
    const float* x  = (const float*)d_in[0];
    const float* qw = (const float*)d_in[1];
    const float* qb = (const float*)d_in[2];
    const float* kw = (const float*)d_in[3];
    const float* kb = (const float*)d_in[4];
    const float* vw = (const float*)d_in[5];
    const float* vb = (const float*)d_in[6];
    const float* ow = (const float*)d_in[7];
    const float* ob = (const float*)d_in[8];
    float* out = (float*)d_out;

    dim3 gblk(256);
    dim3 ggrd(DD / 128, MDIM / 128);   // (8, 32)

    gemm_tc<<<ggrd, gblk>>>(x, qw, qb, nullptr, 0);
    gemm_tc<<<ggrd, gblk>>>(x, kw, kb, nullptr, 1);
    gemm_tc<<<ggrd, gblk>>>(x, vw, vb, nullptr, 2);

    attn_tc<<<dim3(SS / 64, BB * HH), 128>>>();

    gemm_tc<<<ggrd, gblk>>>(x /*ignored*/, ow, ob, out, 3);
}